// round 1
// baseline (speedup 1.0000x reference)
#include <cuda_runtime.h>
#include <math.h>

// Problem constants
#define NB 2
#define LT 6400          // H0*W0
#define ST 6400          // H1*W1
#define CT 256
#define GW 80            // grid width/height
#define BORDER 2
#define SCALE 0.0390625f // 1/(256*0.1)
#define THRESH 0.2f
#define NEG_INF (-1e30f)
#define LCH 32           // l-chunks for column reductions
#define LPER (LT / LCH)  // 200

static const size_t TOT = (size_t)NB * LT * ST; // 81,920,000

// Scratch (static __device__ arrays: allocation-free per harness rules)
__device__ float g_sim[(size_t)NB * LT * ST];
__device__ float g_conf[(size_t)NB * LT * ST];
__device__ float g_rowmax[NB * LT];
__device__ float g_rowinv[NB * LT];
__device__ float g_colmax[NB * ST];
__device__ float g_colinv[NB * ST];
__device__ float g_crowmax[NB * LT];
__device__ float g_ccolmax[NB * ST];
__device__ float g_pm[NB * LCH * ST];
__device__ float g_ps[NB * LCH * ST];
__device__ float g_pcm[NB * LCH * ST];

// ---------------- reductions ----------------
__device__ __forceinline__ float warpMax(float v) {
#pragma unroll
    for (int o = 16; o > 0; o >>= 1) v = fmaxf(v, __shfl_xor_sync(0xffffffffu, v, o));
    return v;
}
__device__ __forceinline__ float warpSum(float v) {
#pragma unroll
    for (int o = 16; o > 0; o >>= 1) v += __shfl_xor_sync(0xffffffffu, v, o);
    return v;
}
__device__ __forceinline__ float blockReduceMax(float v) {
    __shared__ float sh[8];
    __shared__ float res;
    int lane = threadIdx.x & 31, w = threadIdx.x >> 5;
    v = warpMax(v);
    if (lane == 0) sh[w] = v;
    __syncthreads();
    if (w == 0) {
        float t = (lane < 8) ? sh[lane] : NEG_INF;
        t = warpMax(t);
        if (lane == 0) res = t;
    }
    __syncthreads();
    return res;
}
__device__ __forceinline__ float blockReduceSum(float v) {
    __shared__ float sh[8];
    __shared__ float res;
    int lane = threadIdx.x & 31, w = threadIdx.x >> 5;
    v = warpSum(v);
    if (lane == 0) sh[w] = v;
    __syncthreads();
    if (w == 0) {
        float t = (lane < 8) ? sh[lane] : 0.0f;
        t = warpSum(t);
        if (lane == 0) res = t;
    }
    __syncthreads();
    return res;
}

// ---------------- K1: SGEMM sim = x0 . x1^T * SCALE ----------------
// 128x128 tile, BK=8, 256 threads, 8x8 microtile
__global__ __launch_bounds__(256) void gemm_kernel(const float* __restrict__ A,
                                                   const float* __restrict__ B) {
    const int n = blockIdx.z;
    const int bm = blockIdx.y * 128; // l base
    const int bn = blockIdx.x * 128; // s base
    const float* An = A + (size_t)n * LT * CT;
    const float* Bn = B + (size_t)n * ST * CT;
    float* Cn = g_sim + (size_t)n * LT * ST;

    __shared__ float As[8][128];
    __shared__ float Bs[8][128];

    const int tid = threadIdx.x;
    const int lr = tid >> 1;        // 0..127
    const int lc = (tid & 1) * 4;   // 0 or 4
    const int ty = tid >> 4;        // 0..15
    const int tx = tid & 15;        // 0..15

    float acc[8][8];
#pragma unroll
    for (int i = 0; i < 8; i++)
#pragma unroll
        for (int j = 0; j < 8; j++) acc[i][j] = 0.0f;

    for (int k0 = 0; k0 < CT; k0 += 8) {
        float4 a4 = *(const float4*)(An + (size_t)(bm + lr) * CT + k0 + lc);
        float4 b4 = *(const float4*)(Bn + (size_t)(bn + lr) * CT + k0 + lc);
        As[lc + 0][lr] = a4.x; As[lc + 1][lr] = a4.y;
        As[lc + 2][lr] = a4.z; As[lc + 3][lr] = a4.w;
        Bs[lc + 0][lr] = b4.x; Bs[lc + 1][lr] = b4.y;
        Bs[lc + 2][lr] = b4.z; Bs[lc + 3][lr] = b4.w;
        __syncthreads();
#pragma unroll
        for (int k = 0; k < 8; k++) {
            float ar[8], br[8];
            *(float4*)(ar)     = *(const float4*)(&As[k][ty * 8]);
            *(float4*)(ar + 4) = *(const float4*)(&As[k][ty * 8 + 4]);
            *(float4*)(br)     = *(const float4*)(&Bs[k][tx * 8]);
            *(float4*)(br + 4) = *(const float4*)(&Bs[k][tx * 8 + 4]);
#pragma unroll
            for (int i = 0; i < 8; i++)
#pragma unroll
                for (int j = 0; j < 8; j++) acc[i][j] = fmaf(ar[i], br[j], acc[i][j]);
        }
        __syncthreads();
    }

#pragma unroll
    for (int i = 0; i < 8; i++) {
        size_t off = (size_t)(bm + ty * 8 + i) * ST + bn + tx * 8;
        float4 v0 = make_float4(acc[i][0] * SCALE, acc[i][1] * SCALE,
                                acc[i][2] * SCALE, acc[i][3] * SCALE);
        float4 v1 = make_float4(acc[i][4] * SCALE, acc[i][5] * SCALE,
                                acc[i][6] * SCALE, acc[i][7] * SCALE);
        *(float4*)(Cn + off) = v0;
        *(float4*)(Cn + off + 4) = v1;
    }
}

// ---------------- K2: per-row softmax stats (max + sum, one read) ----------------
__global__ __launch_bounds__(256) void rowstats_kernel() {
    const int l = blockIdx.x, n = blockIdx.y;
    const float4* row = (const float4*)(g_sim + ((size_t)n * LT + l) * ST);
    __shared__ float4 srow[ST / 4]; // 25.6 KB
    float m = NEG_INF;
    for (int s = threadIdx.x; s < ST / 4; s += 256) {
        float4 v = row[s];
        srow[s] = v;
        m = fmaxf(fmaxf(fmaxf(m, v.x), v.y), fmaxf(v.z, v.w));
    }
    m = blockReduceMax(m);
    float sum = 0.0f;
    for (int s = threadIdx.x; s < ST / 4; s += 256) {
        float4 v = srow[s];
        sum += __expf(v.x - m) + __expf(v.y - m) + __expf(v.z - m) + __expf(v.w - m);
    }
    sum = blockReduceSum(sum);
    if (threadIdx.x == 0) {
        g_rowmax[n * LT + l] = m;
        g_rowinv[n * LT + l] = 1.0f / sum;
    }
}

// ---------------- K3: column softmax stats (two-stage, online) ----------------
__global__ __launch_bounds__(256) void colpart_kernel() {
    const int s = blockIdx.x * 256 + threadIdx.x;
    const int ly = blockIdx.y, n = blockIdx.z;
    const float* base = g_sim + (size_t)n * LT * ST + (size_t)(ly * LPER) * ST + s;
    float m = NEG_INF, sum = 0.0f;
#pragma unroll 4
    for (int i = 0; i < LPER; i++) {
        float v = base[(size_t)i * ST];
        if (v <= m) {
            sum += __expf(v - m);
        } else {
            sum = sum * __expf(m - v) + 1.0f;
            m = v;
        }
    }
    size_t o = (size_t)(n * LCH + ly) * ST + s;
    g_pm[o] = m;
    g_ps[o] = sum;
}

__global__ __launch_bounds__(256) void colmerge_kernel() {
    const int s = blockIdx.x * 256 + threadIdx.x;
    const int n = blockIdx.y;
    float M = NEG_INF;
#pragma unroll
    for (int i = 0; i < LCH; i++) M = fmaxf(M, g_pm[(size_t)(n * LCH + i) * ST + s]);
    float sum = 0.0f;
#pragma unroll
    for (int i = 0; i < LCH; i++) {
        size_t o = (size_t)(n * LCH + i) * ST + s;
        sum += g_ps[o] * __expf(g_pm[o] - M);
    }
    g_colmax[n * ST + s] = M;
    g_colinv[n * ST + s] = 1.0f / sum;
}

// ---------------- K4: confidence + per-row conf max ----------------
__global__ __launch_bounds__(256) void confrow_kernel() {
    const int l = blockIdx.x, n = blockIdx.y;
    const float rm = g_rowmax[n * LT + l];
    const float ri = g_rowinv[n * LT + l];
    const float4* row = (const float4*)(g_sim + ((size_t)n * LT + l) * ST);
    float4* orow = (float4*)(g_conf + ((size_t)n * LT + l) * ST);
    const float4* cm4 = (const float4*)(g_colmax + (size_t)n * ST);
    const float4* ci4 = (const float4*)(g_colinv + (size_t)n * ST);
    float m = NEG_INF;
    for (int s = threadIdx.x; s < ST / 4; s += 256) {
        float4 v = row[s], cm = cm4[s], ci = ci4[s];
        float4 c;
        c.x = __expf(2.0f * v.x - rm - cm.x) * ri * ci.x;
        c.y = __expf(2.0f * v.y - rm - cm.y) * ri * ci.y;
        c.z = __expf(2.0f * v.z - rm - cm.z) * ri * ci.z;
        c.w = __expf(2.0f * v.w - rm - cm.w) * ri * ci.w;
        orow[s] = c;
        m = fmaxf(fmaxf(fmaxf(m, c.x), c.y), fmaxf(c.z, c.w));
    }
    m = blockReduceMax(m);
    if (threadIdx.x == 0) g_crowmax[n * LT + l] = m;
}

// ---------------- K5: per-column conf max (two-stage) ----------------
__global__ __launch_bounds__(256) void ccolpart_kernel() {
    const int s = blockIdx.x * 256 + threadIdx.x;
    const int ly = blockIdx.y, n = blockIdx.z;
    const float* base = g_conf + (size_t)n * LT * ST + (size_t)(ly * LPER) * ST + s;
    float m = NEG_INF;
#pragma unroll 4
    for (int i = 0; i < LPER; i++) m = fmaxf(m, base[(size_t)i * ST]);
    g_pcm[(size_t)(n * LCH + ly) * ST + s] = m;
}

__global__ __launch_bounds__(256) void ccolmerge_kernel() {
    const int s = blockIdx.x * 256 + threadIdx.x;
    const int n = blockIdx.y;
    float M = NEG_INF;
#pragma unroll
    for (int i = 0; i < LCH; i++) M = fmaxf(M, g_pcm[(size_t)(n * LCH + i) * ST + s]);
    g_ccolmax[n * ST + s] = M;
}

// ---------------- K6: finalize (conf copy + mask + scores) ----------------
__global__ __launch_bounds__(256) void finalize_kernel(float* __restrict__ out,
                                                       int write_mask_scores) {
    const unsigned i = (blockIdx.x * 256u + threadIdx.x) * 4u; // element index
    const unsigned s = i % ST;
    const unsigned l = (i / ST) % LT;
    const unsigned n = i / ((unsigned)LT * ST);

    const int h0 = (int)(l / GW), w0 = (int)(l % GW);
    const bool vl = (h0 >= BORDER) && (h0 < GW - BORDER) && (w0 >= BORDER) && (w0 < GW - BORDER);
    const float rm = g_crowmax[n * LT + l];

    const float4 c = *(const float4*)(g_conf + (size_t)i);
    float cv[4] = {c.x, c.y, c.z, c.w};
    float mk[4], sc[4];
    const int h1 = (int)(s / GW);
    const bool vh1 = (h1 >= BORDER) && (h1 < GW - BORDER);
#pragma unroll
    for (int j = 0; j < 4; j++) {
        const int w1 = (int)(s % GW) + j;
        const bool vs = vh1 && (w1 >= BORDER) && (w1 < GW - BORDER);
        const float cc = g_ccolmax[n * ST + s + j];
        const bool ok = (cv[j] > THRESH) && vl && vs && (cv[j] == rm) && (cv[j] == cc);
        mk[j] = ok ? 1.0f : 0.0f;
        sc[j] = ok ? cv[j] : 0.0f;
    }
    // confidence region
    *(float4*)(out + (size_t)i) = c;
    if (write_mask_scores) {
        *(float4*)(out + (size_t)NB * LT * ST + i) = make_float4(mk[0], mk[1], mk[2], mk[3]);
        *(float4*)(out + 2 * (size_t)NB * LT * ST + i) = make_float4(sc[0], sc[1], sc[2], sc[3]);
    }
}

// ---------------- host ----------------
extern "C" void kernel_launch(void* const* d_in, const int* in_sizes, int n_in,
                              void* d_out, int out_size) {
    const float* x0 = (const float*)d_in[0];
    const float* x1 = (const float*)d_in[1];
    float* out = (float*)d_out;

    dim3 gGemm(ST / 128, LT / 128, NB);
    gemm_kernel<<<gGemm, 256>>>(x0, x1);

    rowstats_kernel<<<dim3(LT, NB), 256>>>();

    colpart_kernel<<<dim3(ST / 256, LCH, NB), 256>>>();
    colmerge_kernel<<<dim3(ST / 256, NB), 256>>>();

    confrow_kernel<<<dim3(LT, NB), 256>>>();

    ccolpart_kernel<<<dim3(ST / 256, LCH, NB), 256>>>();
    ccolmerge_kernel<<<dim3(ST / 256, NB), 256>>>();

    const size_t tot = (size_t)NB * LT * ST;
    int write_ms = (out_size >= (long long)(3 * tot)) ? 1 : 0;
    finalize_kernel<<<(unsigned)(tot / 4 / 256), 256>>>(out, write_ms);
}

// round 3
// speedup vs baseline: 1.8081x; 1.8081x over previous
#include <cuda_runtime.h>
#include <cuda_bf16.h>
#include <math.h>
#include <stdint.h>

// Problem constants
#define NB 2
#define LT 6400
#define ST 6400
#define CT 256
#define GW 80
#define BORDER 2
#define SQ 0.19764235f   // sqrt(1/(256*0.1)); SQ*SQ == SCALE to ~5e-9
#define THRESH 0.2f
#define NTIL 50          // 6400/128 tiles per dim
#define LCH 32           // l-chunks in conf pass
#define LPER (LT / LCH)  // 200
#define SBLK 25          // s-blocks in conf pass (6400/256)

// ---------------- scratch ----------------
__device__ float g_sim[(size_t)NB * LT * ST];          // stores E = exp(sim)
__device__ float g_rowinv[NB * LT];
__device__ float g_colinv[NB * ST];
__device__ float g_crowmax[NB * LT];
__device__ float g_ccolmax[NB * ST];
__device__ float g_prs[(size_t)NB * LT * NTIL];        // row partial sums of E
__device__ float g_pcs[(size_t)NB * NTIL * ST];        // col partial sums of E
__device__ float g_pcm[(size_t)NB * LCH * ST];         // conf col-max partials
__device__ float g_crp[(size_t)NB * LT * SBLK];        // conf row-max partials
// bf16 hi/lo split inputs
__device__ uint4 g_h0[(size_t)NB * LT * CT / 8];
__device__ uint4 g_l0[(size_t)NB * LT * CT / 8];
__device__ uint4 g_h1[(size_t)NB * ST * CT / 8];
__device__ uint4 g_l1[(size_t)NB * ST * CT / 8];

// ---------------- helpers ----------------
__device__ __forceinline__ uint32_t smem_u32(const void* p) {
    uint32_t a;
    asm("{ .reg .u64 t; cvta.to.shared.u64 t, %1; cvt.u32.u64 %0, t; }" : "=r"(a) : "l"(p));
    return a;
}
__device__ __forceinline__ void cpa16(uint32_t dst, const void* src) {
    asm volatile("cp.async.cg.shared.global [%0], [%1], 16;" :: "r"(dst), "l"(src));
}
#define CP_COMMIT() asm volatile("cp.async.commit_group;")
#define CP_WAIT1()  asm volatile("cp.async.wait_group 1;")
#define CP_WAIT0()  asm volatile("cp.async.wait_group 0;")

__device__ __forceinline__ void ldsm_x4(uint32_t* r, uint32_t addr) {
    asm volatile("ldmatrix.sync.aligned.m8n8.x4.shared.b16 {%0,%1,%2,%3}, [%4];"
        : "=r"(r[0]), "=r"(r[1]), "=r"(r[2]), "=r"(r[3]) : "r"(addr));
}
__device__ __forceinline__ void ldsm_x2(uint32_t* r, uint32_t addr) {
    asm volatile("ldmatrix.sync.aligned.m8n8.x2.shared.b16 {%0,%1}, [%2];"
        : "=r"(r[0]), "=r"(r[1]) : "r"(addr));
}
__device__ __forceinline__ void mma16816(float* d, const uint32_t* a, const uint32_t* b) {
    asm volatile(
        "mma.sync.aligned.m16n8k16.row.col.f32.bf16.bf16.f32 "
        "{%0,%1,%2,%3}, {%4,%5,%6,%7}, {%8,%9}, {%0,%1,%2,%3};"
        : "+f"(d[0]), "+f"(d[1]), "+f"(d[2]), "+f"(d[3])
        : "r"(a[0]), "r"(a[1]), "r"(a[2]), "r"(a[3]), "r"(b[0]), "r"(b[1]));
}

// ---------------- K0: fp32 -> scaled bf16 hi/lo split ----------------
__device__ __forceinline__ uint32_t pack2(float a, float b) {
    __nv_bfloat162 t = __floats2bfloat162_rn(a, b);
    return *(uint32_t*)&t;
}
__global__ __launch_bounds__(256) void prep_kernel(const float4* __restrict__ x0,
                                                   const float4* __restrict__ x1) {
    int i = blockIdx.x * 256 + threadIdx.x;
    float4 a = x0[i], b = x1[i];
    float av[4] = {a.x * SQ, a.y * SQ, a.z * SQ, a.w * SQ};
    float bv[4] = {b.x * SQ, b.y * SQ, b.z * SQ, b.w * SQ};
    float ah[4], al[4], bh[4], bl[4];
#pragma unroll
    for (int j = 0; j < 4; j++) {
        __nv_bfloat16 h = __float2bfloat16(av[j]);
        ah[j] = __bfloat162float(h);
        al[j] = av[j] - ah[j];
        h = __float2bfloat16(bv[j]);
        bh[j] = __bfloat162float(h);
        bl[j] = bv[j] - bh[j];
    }
    ((uint2*)g_h0)[i] = make_uint2(pack2(ah[0], ah[1]), pack2(ah[2], ah[3]));
    ((uint2*)g_l0)[i] = make_uint2(pack2(al[0], al[1]), pack2(al[2], al[3]));
    ((uint2*)g_h1)[i] = make_uint2(pack2(bh[0], bh[1]), pack2(bh[2], bh[3]));
    ((uint2*)g_l1)[i] = make_uint2(pack2(bl[0], bl[1]), pack2(bl[2], bl[3]));
}

// ---------------- K1: HMMA GEMM, E=exp(sim), fused row/col partial sums ----------------
#define BK 32
#define KCHUNKS (CT / BK)       // 8
#define ASTR 40                 // bf16 elems per smem row (80B, conflict-free ldmatrix)
#define TILE_B (128 * ASTR * 2) // 10240 bytes per operand tile
#define STG_B (4 * TILE_B)      // 40960 per stage
#define ESTR 132                // epilogue f32 tile stride

extern __shared__ char dsm[];

__global__ __launch_bounds__(256, 2) void gemm_mma_kernel() {
    const int n = blockIdx.z;
    const int bm = blockIdx.y * 128;
    const int bn = blockIdx.x * 128;
    const int tid = threadIdx.x;
    const int wid = tid >> 5;
    const int lane = tid & 31;
    const uint32_t sb = smem_u32(dsm);

    const int wm = wid & 3;   // warp m block (32 rows)
    const int wn = wid >> 2;  // warp n block (64 cols)

    float acc[2][8][4];
#pragma unroll
    for (int mi = 0; mi < 2; mi++)
#pragma unroll
        for (int nj = 0; nj < 8; nj++)
#pragma unroll
            for (int q = 0; q < 4; q++) acc[mi][nj][q] = 0.0f;

    // source rows (uint4 units, row stride = CT/8 = 32)
    const int lrow = tid >> 1;          // 0..127
    const int lq0 = (tid & 1) * 2;      // 0 or 2 (two uint4 each)
    const size_t aoff = (size_t)(n * LT + bm + lrow) * 32;
    const size_t boff = (size_t)(n * ST + bn + lrow) * 32;
    const uint32_t drow = (uint32_t)(lrow * (ASTR * 2));

    // ---- loader: chunk c into stage s ----
    auto load_chunk = [&](int c, int s) {
        uint32_t base = sb + s * STG_B;
        const uint4* pA = g_h0 + aoff + c * 4 + lq0;
        const uint4* pAl = g_l0 + aoff + c * 4 + lq0;
        const uint4* pB = g_h1 + boff + c * 4 + lq0;
        const uint4* pBl = g_l1 + boff + c * 4 + lq0;
#pragma unroll
        for (int q = 0; q < 2; q++) {
            uint32_t d = base + drow + (lq0 + q) * 16;
            cpa16(d, pA + q);
            cpa16(d + TILE_B, pAl + q);
            cpa16(d + 2 * TILE_B, pB + q);
            cpa16(d + 3 * TILE_B, pBl + q);
        }
    };

    load_chunk(0, 0);
    CP_COMMIT();

    for (int c = 0; c < KCHUNKS; c++) {
        const int s = c & 1;
        if (c < KCHUNKS - 1) {
            load_chunk(c + 1, s ^ 1);
            CP_COMMIT();
            CP_WAIT1();
        } else {
            CP_WAIT0();
        }
        __syncthreads();

        const uint32_t AH = sb + s * STG_B;
        const uint32_t AL = AH + TILE_B;
        const uint32_t BH = AH + 2 * TILE_B;
        const uint32_t BL = AH + 3 * TILE_B;

#pragma unroll
        for (int kk = 0; kk < 2; kk++) {
            const int k0 = kk * 16;
            // A fragments
            const int rA = wm * 32 + ((lane >> 3) & 1) * 8 + (lane & 7);
            const int kA = k0 + (lane >> 4) * 8;
            uint32_t ah[2][4], al[2][4];
#pragma unroll
            for (int mi = 0; mi < 2; mi++) {
                uint32_t addr = (uint32_t)((rA + mi * 16) * (ASTR * 2) + kA * 2);
                ldsm_x4(ah[mi], AH + addr);
                ldsm_x4(al[mi], AL + addr);
            }
            const int l16 = lane & 15;
            const int rBo = (l16 & 7);
            const int kB = k0 + ((l16 >> 3) & 1) * 8;
#pragma unroll
            for (int nj = 0; nj < 8; nj++) {
                uint32_t addr = (uint32_t)((wn * 64 + nj * 8 + rBo) * (ASTR * 2) + kB * 2);
                uint32_t bh[2], bl[2];
                ldsm_x2(bh, BH + addr);
                ldsm_x2(bl, BL + addr);
#pragma unroll
                for (int mi = 0; mi < 2; mi++) {
                    mma16816(acc[mi][nj], ah[mi], bh);
                    mma16816(acc[mi][nj], ah[mi], bl);
                    mma16816(acc[mi][nj], al[mi], bh);
                }
            }
        }
        __syncthreads();
    }

    // ---- epilogue: E = exp(acc) -> smem tile -> store + partial sums ----
    float* et = (float*)dsm;  // 128 x ESTR floats (67584 B < 81920)
#pragma unroll
    for (int mi = 0; mi < 2; mi++) {
        const int r1 = wm * 32 + mi * 16 + (lane >> 2);
#pragma unroll
        for (int nj = 0; nj < 8; nj++) {
            const int cc = wn * 64 + nj * 8 + 2 * (lane & 3);
            et[r1 * ESTR + cc]           = __expf(acc[mi][nj][0]);
            et[r1 * ESTR + cc + 1]       = __expf(acc[mi][nj][1]);
            et[(r1 + 8) * ESTR + cc]     = __expf(acc[mi][nj][2]);
            et[(r1 + 8) * ESTR + cc + 1] = __expf(acc[mi][nj][3]);
        }
    }
    __syncthreads();

    // coalesced store of E tile
    float* Cn = g_sim + (size_t)n * LT * ST;
#pragma unroll
    for (int i = 0; i < 16; i++) {
        int idx = i * 256 + tid;
        int row = idx >> 5;
        int q = idx & 31;
        float4 v = *(float4*)(et + row * ESTR + q * 4);
        *(float4*)(Cn + (size_t)(bm + row) * ST + bn + q * 4) = v;
    }

    // row partial sums: 2 threads per row
    {
        int row = tid >> 1, h = tid & 1;
        float s = 0.0f;
        const float* p = et + row * ESTR + h * 64;
#pragma unroll 16
        for (int j = 0; j < 64; j++) s += p[j];
        s += __shfl_xor_sync(0xffffffffu, s, 1);
        if (h == 0) g_prs[(size_t)(n * LT + bm + row) * NTIL + blockIdx.x] = s;
    }
    // col partial sums: 2 threads per col
    {
        int col = tid >> 1, h = tid & 1;
        float s = 0.0f;
        const float* p = et + (h * 64) * ESTR + col;
#pragma unroll 16
        for (int j = 0; j < 64; j++) s += p[j * ESTR];
        s += __shfl_xor_sync(0xffffffffu, s, 1);
        if (h == 0) g_pcs[((size_t)n * NTIL + blockIdx.y) * ST + bn + col] = s;
    }
}

// ---------------- small merges ----------------
__global__ __launch_bounds__(256) void rowsum_merge() {
    int i = blockIdx.x * 256 + threadIdx.x;
    if (i >= NB * LT) return;
    const float* p = g_prs + (size_t)i * NTIL;
    float s = 0.0f;
#pragma unroll 10
    for (int t = 0; t < NTIL; t++) s += p[t];
    g_rowinv[i] = 1.0f / s;
}
__global__ __launch_bounds__(256) void colsum_merge() {
    int i = blockIdx.x * 256 + threadIdx.x;
    if (i >= NB * ST) return;
    int n = i / ST, s = i % ST;
    float sum = 0.0f;
#pragma unroll 10
    for (int t = 0; t < NTIL; t++) sum += g_pcs[((size_t)n * NTIL + t) * ST + s];
    g_colinv[i] = 1.0f / sum;
}

// ---------------- conf pass: conf = E^2 * rinv * cinv, fused max partials ----------------
__global__ __launch_bounds__(256) void conf_kernel(float* __restrict__ out) {
    const int s = blockIdx.x * 256 + threadIdx.x;
    const int by = blockIdx.y, n = blockIdx.z;
    const int lane = threadIdx.x & 31, wid = threadIdx.x >> 5;
    const float ci = g_colinv[n * ST + s];
    __shared__ float wm[8][LPER];

    const size_t base = (size_t)n * LT * ST + (size_t)(by * LPER) * ST + s;
    const float* Eb = g_sim + base;
    float* Ob = out + base;
    float cmax = 0.0f;
    for (int i = 0; i < LPER; i++) {
        const int row = by * LPER + i;
        const float ri = g_rowinv[n * LT + row];
        float E = Eb[(size_t)i * ST];
        float c = E * E * ri * ci;
        Ob[(size_t)i * ST] = c;
        cmax = fmaxf(cmax, c);
        float w = c;
#pragma unroll
        for (int o = 16; o > 0; o >>= 1) w = fmaxf(w, __shfl_xor_sync(0xffffffffu, w, o));
        if (lane == 0) wm[wid][i] = w;
    }
    g_pcm[((size_t)(n * LCH + by)) * ST + s] = cmax;
    __syncthreads();
    for (int i = threadIdx.x; i < LPER; i += 256) {
        float m = wm[0][i];
#pragma unroll
        for (int w = 1; w < 8; w++) m = fmaxf(m, wm[w][i]);
        g_crp[((size_t)n * LT + by * LPER + i) * SBLK + blockIdx.x] = m;
    }
}

__global__ __launch_bounds__(256) void crow_merge() {
    int i = blockIdx.x * 256 + threadIdx.x;
    if (i >= NB * LT) return;
    const float* p = g_crp + (size_t)i * SBLK;
    float m = 0.0f;
#pragma unroll
    for (int t = 0; t < SBLK; t++) m = fmaxf(m, p[t]);
    g_crowmax[i] = m;
}
__global__ __launch_bounds__(256) void ccol_merge() {
    int i = blockIdx.x * 256 + threadIdx.x;
    if (i >= NB * ST) return;
    int n = i / ST, s = i % ST;
    float m = 0.0f;
#pragma unroll
    for (int t = 0; t < LCH; t++) m = fmaxf(m, g_pcm[((size_t)(n * LCH + t)) * ST + s]);
    g_ccolmax[i] = m;
}

// ---------------- finalize: mask + scores ----------------
__global__ __launch_bounds__(256) void finalize_kernel(float* __restrict__ out,
                                                       int write_mask_scores) {
    const unsigned i = (blockIdx.x * 256u + threadIdx.x) * 4u;
    const unsigned s = i % ST;
    const unsigned l = (i / ST) % LT;
    const unsigned n = i / ((unsigned)LT * ST);

    const int h0 = (int)(l / GW), w0 = (int)(l % GW);
    const bool vl = (h0 >= BORDER) && (h0 < GW - BORDER) && (w0 >= BORDER) && (w0 < GW - BORDER);
    const float rm = g_crowmax[n * LT + l];

    const float4 c = *(const float4*)(out + (size_t)i);  // conf written by conf_kernel
    float cv[4] = {c.x, c.y, c.z, c.w};
    float mk[4], sc[4];
    const int h1 = (int)(s / GW);
    const bool vh1 = (h1 >= BORDER) && (h1 < GW - BORDER);
#pragma unroll
    for (int j = 0; j < 4; j++) {
        const int w1 = (int)(s % GW) + j;
        const bool vs = vh1 && (w1 >= BORDER) && (w1 < GW - BORDER);
        const float cc = g_ccolmax[n * ST + s + j];
        const bool ok = (cv[j] > THRESH) && vl && vs && (cv[j] == rm) && (cv[j] == cc);
        mk[j] = ok ? 1.0f : 0.0f;
        sc[j] = ok ? cv[j] : 0.0f;
    }
    if (write_mask_scores) {
        *(float4*)(out + (size_t)NB * LT * ST + i) = make_float4(mk[0], mk[1], mk[2], mk[3]);
        *(float4*)(out + 2 * (size_t)NB * LT * ST + i) = make_float4(sc[0], sc[1], sc[2], sc[3]);
    }
}

// ---------------- host ----------------
extern "C" void kernel_launch(void* const* d_in, const int* in_sizes, int n_in,
                              void* d_out, int out_size) {
    const float* x0 = (const float*)d_in[0];
    const float* x1 = (const float*)d_in[1];
    float* out = (float*)d_out;

    static int smem_set = 0;
    if (!smem_set) {
        cudaFuncSetAttribute(gemm_mma_kernel, cudaFuncAttributeMaxDynamicSharedMemorySize,
                             2 * STG_B);
        smem_set = 1;
    }

    prep_kernel<<<(NB * LT * CT / 4) / 256, 256>>>((const float4*)x0, (const float4*)x1);

    gemm_mma_kernel<<<dim3(NTIL, NTIL, NB), 256, 2 * STG_B>>>();

    rowsum_merge<<<(NB * LT + 255) / 256, 256>>>();
    colsum_merge<<<(NB * ST + 255) / 256, 256>>>();

    conf_kernel<<<dim3(SBLK, LCH, NB), 256>>>(out);

    crow_merge<<<(NB * LT + 255) / 256, 256>>>();
    ccol_merge<<<(NB * ST + 255) / 256, 256>>>();

    const size_t tot = (size_t)NB * LT * ST;
    int write_ms = (out_size >= (long long)(3 * tot)) ? 1 : 0;
    finalize_kernel<<<(unsigned)(tot / 4 / 256), 256>>>(out, write_ms);
}